// round 1
// baseline (speedup 1.0000x reference)
#include <cuda_runtime.h>

#define Bdim  32
#define Hdim  256
#define INdim 256
#define T_MAX 2048
#define KS    224            // W_rec^T rows kept in shared memory
#define KR    32             // W_rec^T rows kept in per-thread registers
#define LOOP_SMEM (KS * Hdim * 4 + 16 * 4)

// Precomputed input currents Iin[t][b][h] = x[t,b,:] . W_in[h,:]
__device__ float g_Iin[(size_t)T_MAX * Bdim * Hdim];

// ---------------------------------------------------------------------------
// Phase 1: fp32 GEMM  C[m][h] = sum_k A[m][k] * W[h][k]   (NT, both K-major)
// M = T*B rows, K = 256, N = 256. Classic 128x128x32 smem-tiled FFMA GEMM.
// ---------------------------------------------------------------------------
__global__ __launch_bounds__(256) void in_gemm_kernel(
    const float* __restrict__ A, const float* __restrict__ W, int M)
{
    __shared__ float As[32][128 + 4];
    __shared__ float Bs[32][128 + 4];
    const int tid = threadIdx.x;
    const int m0 = blockIdx.x * 128;
    const int n0 = blockIdx.y * 128;
    const int tx = tid & 15;   // n micro-tile
    const int ty = tid >> 4;   // m micro-tile
    float acc[8][8];
#pragma unroll
    for (int r = 0; r < 8; ++r)
#pragma unroll
        for (int c = 0; c < 8; ++c) acc[r][c] = 0.0f;

    for (int k0 = 0; k0 < INdim; k0 += 32) {
#pragma unroll
        for (int i = 0; i < 4; ++i) {
            int idx = tid + i * 256;          // 0..1023, one float4 each
            int row = idx >> 3;               // 0..127
            int c4  = idx & 7;                // 0..7 (groups of 4 k)
            float4 av = *(const float4*)(A + (size_t)(m0 + row) * INdim + k0 + c4 * 4);
            As[c4 * 4 + 0][row] = av.x;
            As[c4 * 4 + 1][row] = av.y;
            As[c4 * 4 + 2][row] = av.z;
            As[c4 * 4 + 3][row] = av.w;
            float4 bv = *(const float4*)(W + (size_t)(n0 + row) * INdim + k0 + c4 * 4);
            Bs[c4 * 4 + 0][row] = bv.x;
            Bs[c4 * 4 + 1][row] = bv.y;
            Bs[c4 * 4 + 2][row] = bv.z;
            Bs[c4 * 4 + 3][row] = bv.w;
        }
        __syncthreads();
#pragma unroll
        for (int k = 0; k < 32; ++k) {
            float a[8], b[8];
#pragma unroll
            for (int u = 0; u < 8; u += 4) {
                float4 t4 = *(const float4*)&As[k][ty * 8 + u];
                a[u] = t4.x; a[u + 1] = t4.y; a[u + 2] = t4.z; a[u + 3] = t4.w;
                float4 s4 = *(const float4*)&Bs[k][tx * 8 + u];
                b[u] = s4.x; b[u + 1] = s4.y; b[u + 2] = s4.z; b[u + 3] = s4.w;
            }
#pragma unroll
            for (int r = 0; r < 8; ++r)
#pragma unroll
                for (int c = 0; c < 8; ++c)
                    acc[r][c] = fmaf(a[r], b[c], acc[r][c]);
        }
        __syncthreads();
    }
#pragma unroll
    for (int r = 0; r < 8; ++r)
#pragma unroll
        for (int c = 0; c < 8; c += 4) {
            float4 o = make_float4(acc[r][c], acc[r][c + 1], acc[r][c + 2], acc[r][c + 3]);
            *(float4*)(g_Iin + (size_t)(m0 + ty * 8 + r) * Hdim + n0 + tx * 8 + c) = o;
        }
}

// ---------------------------------------------------------------------------
// Phase 2: sequential LIF recurrence. 1 CTA per batch, 1 thread per neuron.
// Per step:
//   v_dec = v + 0.1*((0 - v) + i);  i_dec = i - 0.2*i
//   z_new = (v_dec - 1) > 0;  v_new = z ? 0 : v_dec
//   i_new = (i_dec + Iin[t]) + (z_prev @ Wrec^T)    <- prev step's spikes!
// z is exchanged via warp ballots in double-buffered smem masks; one
// __syncthreads per step. Recurrent term = exact sparse gather of Wrec
// columns (z binary): smem for k<224, registers (predicated FADD) for k>=224.
// ---------------------------------------------------------------------------
__global__ __launch_bounds__(256, 1) void lif_loop_kernel(
    const float* __restrict__ z0, const float* __restrict__ v0,
    const float* __restrict__ i0, const float* __restrict__ Wrec,
    float* __restrict__ out, int T)
{
    extern __shared__ float smem[];
    float* Wsh = smem;                               // [KS][Hdim], Wsh[k][h] = Wrec[h][k]
    unsigned* zs = (unsigned*)(smem + KS * Hdim);    // [2][8] ballot masks
    const int b = blockIdx.x;
    const int j = threadIdx.x;                       // neuron index
    const int warp = j >> 5;
    const int lane = j & 31;

    // Stage transposed Wrec rows [0,KS) into smem (coalesced global reads).
    for (int idx = j; idx < Hdim * Hdim; idx += 256) {
        int h = idx >> 8;
        int k = idx & 255;
        if (k < KS) Wsh[k * Hdim + h] = Wrec[idx];
    }
    // Rows [KS,256) for this thread's column -> registers.
    float wreg[KR];
#pragma unroll
    for (int kk = 0; kk < KR; kk += 4) {
        float4 wv = *(const float4*)(Wrec + (size_t)j * Hdim + KS + kk);
        wreg[kk] = wv.x; wreg[kk + 1] = wv.y; wreg[kk + 2] = wv.z; wreg[kk + 3] = wv.w;
    }

    float v   = v0[b * Hdim + j];
    float cur = i0[b * Hdim + j];
    float zprev = z0[b * Hdim + j];
    unsigned minit = __ballot_sync(0xffffffffu, zprev != 0.0f);
    if (lane == 0) zs[warp] = minit;
    __syncthreads();

    int pb = 0;
    float iin = g_Iin[(size_t)b * Hdim + j];
    bool z = false;
    for (int t = 0; t < T; ++t) {
        // Prefetch next step's input current early (latency hidden by gather).
        float iin_next = 0.0f;
        if (t + 1 < T) iin_next = g_Iin[((size_t)(t + 1) * Bdim + b) * Hdim + j];

        // Sparse recurrent gather from z_{t-1} (exact: skipped terms are 0*w).
        float r0 = 0.0f, r1 = 0.0f;
#pragma unroll
        for (int w = 0; w < 7; ++w) {
            unsigned mm = zs[pb * 8 + w];            // uniform -> no divergence
            const float* wp = Wsh + (w * 32) * Hdim + j;
            while (mm) {
                int bit = __ffs(mm) - 1;
                mm &= mm - 1;
                if (w & 1) r1 += wp[bit * Hdim];
                else       r0 += wp[bit * Hdim];
            }
        }
        unsigned m7 = zs[pb * 8 + 7];
#pragma unroll
        for (int kk = 0; kk < KR; ++kk)
            if ((m7 >> kk) & 1u) r1 += wreg[kk];

        // LIF update (constants match JAX's folded python-float products).
        float v_dec = v + 0.1f * ((0.0f - v) + cur);
        float i_dec = cur - 0.2f * cur;
        z = (v_dec - 1.0f) > 0.0f;
        v = z ? 0.0f : v_dec;
        cur = (i_dec + iin) + (r0 + r1);

        unsigned nm = __ballot_sync(0xffffffffu, z);
        if (lane == 0) zs[(pb ^ 1) * 8 + warp] = nm;
        out[((size_t)t * Bdim + b) * Hdim + j] = z ? 1.0f : 0.0f;
        __syncthreads();                              // publish masks, guard WAR
        pb ^= 1;
        iin = iin_next;
    }

    // Final state: layout = [spikes (T,B,H)][z (B,H)][v (B,H)][i (B,H)]
    size_t base = (size_t)T * Bdim * Hdim;
    out[base + b * Hdim + j] = z ? 1.0f : 0.0f;
    out[base + Bdim * Hdim + b * Hdim + j] = v;
    out[base + 2 * Bdim * Hdim + b * Hdim + j] = cur;
}

extern "C" void kernel_launch(void* const* d_in, const int* in_sizes, int n_in,
                              void* d_out, int out_size)
{
    const float* x    = (const float*)d_in[0];   // (T,B,IN)
    const float* z0   = (const float*)d_in[1];   // (B,H)
    const float* v0   = (const float*)d_in[2];
    const float* i0   = (const float*)d_in[3];
    const float* Win  = (const float*)d_in[4];   // (H,IN)
    const float* Wrec = (const float*)d_in[5];   // (H,H)
    float* out = (float*)d_out;

    int T = in_sizes[0] / (Bdim * INdim);        // 2048
    int M = T * Bdim;                             // 65536

    cudaFuncSetAttribute(lif_loop_kernel,
                         cudaFuncAttributeMaxDynamicSharedMemorySize, LOOP_SMEM);

    in_gemm_kernel<<<dim3(M / 128, Hdim / 128), 256>>>(x, Win, M);
    lif_loop_kernel<<<Bdim, 256, LOOP_SMEM>>>(z0, v0, i0, Wrec, out, T);

    (void)n_in; (void)out_size;
}